// round 1
// baseline (speedup 1.0000x reference)
#include <cuda_runtime.h>
#include <math.h>

#define NN    100000
#define EE    3200000
#define NFEAT 256
#define NHID  128
#define NCLASS 40

// ---------------- scratch (static device globals; no allocation) ----------------
__device__ __align__(16) float g_s1[NN * NHID];     // support1 = x @ W1        (51.2 MB)
__device__ __align__(16) float g_h [NN * NHID];     // h = relu(A@s1 + b1)      (51.2 MB)
__device__ __align__(16) float g_s2[NN * NCLASS];   // s2 = h @ W2              (16 MB)
__device__ int g_rowptr[NN + 1];

// ---------------- CSR row_ptr from sorted adj_row (lower_bound) ----------------
__global__ void build_rowptr_kernel(const int* __restrict__ arow) {
    int r = blockIdx.x * blockDim.x + threadIdx.x;
    if (r > NN) return;
    int lo = 0, hi = EE;
    while (lo < hi) {
        int mid = (lo + hi) >> 1;
        if (arow[mid] < r) lo = mid + 1; else hi = mid;
    }
    g_rowptr[r] = lo;
}

// ---------------- GEMM1: C[N,128] = X[N,256] @ W1[256,128] ----------------
// 64-row x 128-col tile per block, 256 threads, 8x4 register tile, K-tile 32.
#define G1_BM 64
#define G1_BK 32
__global__ void gemm1_kernel(const float* __restrict__ X, const float* __restrict__ W1) {
    __shared__ float As[G1_BM][G1_BK + 1];   // +1 pad
    __shared__ float Bs[G1_BK][NHID];

    const int tid = threadIdx.x;             // 256
    const int tx  = tid & 31;                // col group: cols tx*4 .. tx*4+3
    const int ty  = tid >> 5;                // row group: rows ty*8 .. ty*8+7  (warp = fixed ty -> As broadcast)
    const int row0 = blockIdx.x * G1_BM;

    float acc[8][4];
#pragma unroll
    for (int i = 0; i < 8; i++)
#pragma unroll
        for (int j = 0; j < 4; j++) acc[i][j] = 0.f;

    for (int k0 = 0; k0 < NFEAT; k0 += G1_BK) {
        // load A tile: 64x32 floats, 2 float4 per thread
#pragma unroll
        for (int j = 0; j < 2; j++) {
            int idx = tid * 2 + j;           // float4 index in [0,512)
            int r   = idx >> 3;              // 8 float4 per row
            int c4  = (idx & 7) * 4;
            int grow = row0 + r;
            float4 v = make_float4(0.f, 0.f, 0.f, 0.f);
            if (grow < NN) v = *(const float4*)&X[(size_t)grow * NFEAT + k0 + c4];
            As[r][c4 + 0] = v.x; As[r][c4 + 1] = v.y;
            As[r][c4 + 2] = v.z; As[r][c4 + 3] = v.w;
        }
        // load B tile: 32x128 floats, 4 float4 per thread
#pragma unroll
        for (int j = 0; j < 4; j++) {
            int fi = j * 256 + tid;          // float4 index in [0,1024)
            int r  = fi >> 5;                // 32 float4 per row
            int c  = (fi & 31) * 4;
            *(float4*)&Bs[r][c] = *(const float4*)&W1[(size_t)(k0 + r) * NHID + c];
        }
        __syncthreads();

#pragma unroll
        for (int kk = 0; kk < G1_BK; kk++) {
            float4 bv = *(const float4*)&Bs[kk][tx * 4];
#pragma unroll
            for (int i = 0; i < 8; i++) {
                float a = As[ty * 8 + i][kk];
                acc[i][0] += a * bv.x;
                acc[i][1] += a * bv.y;
                acc[i][2] += a * bv.z;
                acc[i][3] += a * bv.w;
            }
        }
        __syncthreads();
    }

#pragma unroll
    for (int i = 0; i < 8; i++) {
        int grow = row0 + ty * 8 + i;
        if (grow < NN)
            *(float4*)&g_s1[(size_t)grow * NHID + tx * 4] =
                make_float4(acc[i][0], acc[i][1], acc[i][2], acc[i][3]);
    }
}

// ---------------- SpMM1 + bias + ReLU: h = relu(A @ s1 + b1) ----------------
// warp per row; lane handles 4 consecutive hidden dims (float4). 2-edge unroll for MLP.
__global__ void spmm1_kernel(const int* __restrict__ acol, const float* __restrict__ aval,
                             const float* __restrict__ b1) {
    int warp = (blockIdx.x * blockDim.x + threadIdx.x) >> 5;
    int lane = threadIdx.x & 31;
    if (warp >= NN) return;

    int s = g_rowptr[warp];
    int e = g_rowptr[warp + 1];

    const float4* S1v = (const float4*)g_s1;
    float4 acc = make_float4(0.f, 0.f, 0.f, 0.f);

    int i = s;
    for (; i + 1 < e; i += 2) {
        int   c0 = __ldg(&acol[i]);
        int   c1 = __ldg(&acol[i + 1]);
        float v0 = __ldg(&aval[i]);
        float v1 = __ldg(&aval[i + 1]);
        float4 d0 = S1v[(size_t)c0 * 32 + lane];
        float4 d1 = S1v[(size_t)c1 * 32 + lane];
        acc.x += v0 * d0.x + v1 * d1.x;
        acc.y += v0 * d0.y + v1 * d1.y;
        acc.z += v0 * d0.z + v1 * d1.z;
        acc.w += v0 * d0.w + v1 * d1.w;
    }
    if (i < e) {
        int   c0 = __ldg(&acol[i]);
        float v0 = __ldg(&aval[i]);
        float4 d0 = S1v[(size_t)c0 * 32 + lane];
        acc.x += v0 * d0.x; acc.y += v0 * d0.y;
        acc.z += v0 * d0.z; acc.w += v0 * d0.w;
    }

    float4 b = ((const float4*)b1)[lane];
    acc.x = fmaxf(acc.x + b.x, 0.f);
    acc.y = fmaxf(acc.y + b.y, 0.f);
    acc.z = fmaxf(acc.z + b.z, 0.f);
    acc.w = fmaxf(acc.w + b.w, 0.f);
    ((float4*)g_h)[(size_t)warp * 32 + lane] = acc;
}

// ---------------- GEMM2: s2[N,40] = h[N,128] @ W2[128,40] ----------------
// 32 rows per block, 256 threads; W2 + H tile staged in smem; 5 outputs/thread.
__global__ void gemm2_kernel(const float* __restrict__ W2) {
    __shared__ float Ws[NHID * NCLASS];      // 20 KB
    __shared__ float Hs[32][NHID + 1];       // padded

    const int tid  = threadIdx.x;            // 256
    const int row0 = blockIdx.x * 32;

    for (int j = tid; j < NHID * NCLASS; j += 256) Ws[j] = W2[j];

    for (int j = tid; j < 32 * (NHID / 4); j += 256) {
        int r = j >> 5;                      // 32 float4 per row
        int c = (j & 31) * 4;
        int grow = row0 + r;
        float4 v = make_float4(0.f, 0.f, 0.f, 0.f);
        if (grow < NN) v = *(const float4*)&g_h[(size_t)grow * NHID + c];
        Hs[r][c + 0] = v.x; Hs[r][c + 1] = v.y;
        Hs[r][c + 2] = v.z; Hs[r][c + 3] = v.w;
    }
    __syncthreads();

    const int r  = tid >> 3;                 // row within tile
    const int cg = tid & 7;                  // cols cg*5 .. cg*5+4
    float acc[5] = {0.f, 0.f, 0.f, 0.f, 0.f};

#pragma unroll 8
    for (int k = 0; k < NHID; k++) {
        float hv = Hs[r][k];
#pragma unroll
        for (int c = 0; c < 5; c++) acc[c] += hv * Ws[k * NCLASS + cg * 5 + c];
    }

    int grow = row0 + r;
    if (grow < NN) {
#pragma unroll
        for (int c = 0; c < 5; c++) g_s2[(size_t)grow * NCLASS + cg * 5 + c] = acc[c];
    }
}

// ---------------- SpMM2 + bias + log_softmax ----------------
// warp per row; lanes 0..19 hold float2 (2 classes each). Fused row softmax via shuffles.
__global__ void spmm2_lsm_kernel(const int* __restrict__ acol, const float* __restrict__ aval,
                                 const float* __restrict__ b2, float* __restrict__ out) {
    int warp = (blockIdx.x * blockDim.x + threadIdx.x) >> 5;
    int lane = threadIdx.x & 31;
    if (warp >= NN) return;

    int s = g_rowptr[warp];
    int e = g_rowptr[warp + 1];
    bool active = lane < 20;

    const float2* S2v = (const float2*)g_s2;
    float2 acc = make_float2(0.f, 0.f);

    int i = s;
    for (; i + 1 < e; i += 2) {
        int   c0 = __ldg(&acol[i]);
        int   c1 = __ldg(&acol[i + 1]);
        float v0 = __ldg(&aval[i]);
        float v1 = __ldg(&aval[i + 1]);
        if (active) {
            float2 d0 = S2v[(size_t)c0 * 20 + lane];
            float2 d1 = S2v[(size_t)c1 * 20 + lane];
            acc.x += v0 * d0.x + v1 * d1.x;
            acc.y += v0 * d0.y + v1 * d1.y;
        }
    }
    if (i < e) {
        int   c0 = __ldg(&acol[i]);
        float v0 = __ldg(&aval[i]);
        if (active) {
            float2 d0 = S2v[(size_t)c0 * 20 + lane];
            acc.x += v0 * d0.x;
            acc.y += v0 * d0.y;
        }
    }

    if (active) {
        acc.x += __ldg(&b2[2 * lane]);
        acc.y += __ldg(&b2[2 * lane + 1]);
    }

    // row max
    float m = active ? fmaxf(acc.x, acc.y) : -INFINITY;
#pragma unroll
    for (int off = 16; off > 0; off >>= 1)
        m = fmaxf(m, __shfl_xor_sync(0xFFFFFFFFu, m, off));

    // sum exp
    float se = active ? (expf(acc.x - m) + expf(acc.y - m)) : 0.f;
#pragma unroll
    for (int off = 16; off > 0; off >>= 1)
        se += __shfl_xor_sync(0xFFFFFFFFu, se, off);

    float lse = m + logf(se);
    if (active) {
        out[(size_t)warp * NCLASS + 2 * lane]     = acc.x - lse;
        out[(size_t)warp * NCLASS + 2 * lane + 1] = acc.y - lse;
    }
}

// ---------------- launch ----------------
extern "C" void kernel_launch(void* const* d_in, const int* in_sizes, int n_in,
                              void* d_out, int out_size) {
    const float* x    = (const float*)d_in[0];
    const int*   arow = (const int*)  d_in[1];
    const int*   acol = (const int*)  d_in[2];
    const float* aval = (const float*)d_in[3];
    // d_in[4] = i (unused scalar)
    const float* W1 = (const float*)d_in[5];
    const float* b1 = (const float*)d_in[6];
    const float* W2 = (const float*)d_in[7];
    const float* b2 = (const float*)d_in[8];
    float* out = (float*)d_out;

    build_rowptr_kernel<<<(NN + 1 + 255) / 256, 256>>>(arow);
    gemm1_kernel<<<(NN + G1_BM - 1) / G1_BM, 256>>>(x, W1);
    spmm1_kernel<<<(NN * 32 + 255) / 256, 256>>>(acol, aval, b1);
    gemm2_kernel<<<(NN + 31) / 32, 256>>>(W2);
    spmm2_lsm_kernel<<<(NN * 32 + 255) / 256, 256>>>(acol, aval, b2, out);
}

// round 2
// speedup vs baseline: 1.1273x; 1.1273x over previous
#include <cuda_runtime.h>
#include <math.h>

#define NN    100000
#define EE    3200000
#define NFEAT 256
#define NHID  128
#define NCLASS 40

// ---------------- scratch (static device globals; no allocation) ----------------
__device__ __align__(16) float g_s1[NN * NHID];     // support1 = x @ W1
__device__ __align__(16) float g_h [NN * NHID];     // h = relu(A@s1 + b1)
__device__ __align__(16) float g_s2[NN * NCLASS];   // s2 = h @ W2
__device__ int g_rowptr[NN + 1];

// ---------------- f32x2 packed helpers (Blackwell: 2x fp32 FMA throughput) ----------------
__device__ __forceinline__ unsigned long long ffma2(unsigned long long a,
                                                    unsigned long long b,
                                                    unsigned long long c) {
    unsigned long long d;
    asm("fma.rn.f32x2 %0, %1, %2, %3;" : "=l"(d) : "l"(a), "l"(b), "l"(c));
    return d;
}
__device__ __forceinline__ unsigned long long dup2(float a) {
    unsigned long long d;
    asm("mov.b64 %0, {%1, %1};" : "=l"(d) : "f"(a));
    return d;
}
__device__ __forceinline__ float2 unpack2(unsigned long long v) {
    float2 f;
    asm("mov.b64 {%0, %1}, %2;" : "=f"(f.x), "=f"(f.y) : "l"(v));
    return f;
}

// ---------------- CSR row_ptr from sorted adj_row (lower_bound) ----------------
__global__ void build_rowptr_kernel(const int* __restrict__ arow) {
    int r = blockIdx.x * blockDim.x + threadIdx.x;
    if (r > NN) return;
    int lo = 0, hi = EE;
    while (lo < hi) {
        int mid = (lo + hi) >> 1;
        if (arow[mid] < r) lo = mid + 1; else hi = mid;
    }
    g_rowptr[r] = lo;
}

// ---------------- GEMM1: g_s1[N,128] = X[N,256] @ W1[256,128] ----------------
// Block tile 128x128, 256 threads, thread tile 8 rows x 8 cols (4 col-pairs f32x2).
#define G1_BM 128
#define G1_BK 32
#define G1_AS 33   // padded stride for As (conflict-free)
__global__ void __launch_bounds__(256) gemm1_kernel(const float* __restrict__ X,
                                                    const float* __restrict__ W1) {
    __shared__ float As[G1_BM * G1_AS];     // row-major [r][kk], pad 33
    __shared__ float Bs[G1_BK * NHID];      // row-major [kk][c]

    const int tid = threadIdx.x;
    const int tx  = tid & 15;               // col-pair base: cols {2*tx + 32*j}
    const int ty  = tid >> 4;               // rows ty*8 .. ty*8+7
    const int row0 = blockIdx.x * G1_BM;

    unsigned long long acc[8][4];
#pragma unroll
    for (int i = 0; i < 8; i++)
#pragma unroll
        for (int j = 0; j < 4; j++) acc[i][j] = 0ull;

    for (int k0 = 0; k0 < NFEAT; k0 += G1_BK) {
        // X tile: 128x32 floats = 1024 float4, 4 per thread, coalesced
#pragma unroll
        for (int j = 0; j < 4; j++) {
            int fi = j * 256 + tid;
            int r  = fi >> 3;                // 8 float4 per row
            int c4 = (fi & 7) * 4;
            int grow = row0 + r;
            float4 v = make_float4(0.f, 0.f, 0.f, 0.f);
            if (grow < NN) v = *(const float4*)&X[(size_t)grow * NFEAT + k0 + c4];
            As[r * G1_AS + c4 + 0] = v.x;
            As[r * G1_AS + c4 + 1] = v.y;
            As[r * G1_AS + c4 + 2] = v.z;
            As[r * G1_AS + c4 + 3] = v.w;
        }
        // W1 tile: 32x128 floats = 1024 float4, 4 per thread
#pragma unroll
        for (int j = 0; j < 4; j++) {
            int fi = j * 256 + tid;
            int r  = fi >> 5;                // 32 float4 per row
            int c  = (fi & 31) * 4;
            *(float4*)&Bs[r * NHID + c] = *(const float4*)&W1[(size_t)(k0 + r) * NHID + c];
        }
        __syncthreads();

#pragma unroll
        for (int kk = 0; kk < G1_BK; kk++) {
            unsigned long long ad[8];
#pragma unroll
            for (int i = 0; i < 8; i++)
                ad[i] = dup2(As[(ty * 8 + i) * G1_AS + kk]);
            unsigned long long bp[4];
#pragma unroll
            for (int j = 0; j < 4; j++)
                bp[j] = *(const unsigned long long*)&Bs[kk * NHID + 2 * tx + 32 * j];
#pragma unroll
            for (int i = 0; i < 8; i++)
#pragma unroll
                for (int j = 0; j < 4; j++)
                    acc[i][j] = ffma2(ad[i], bp[j], acc[i][j]);
        }
        __syncthreads();
    }

#pragma unroll
    for (int i = 0; i < 8; i++) {
        int grow = row0 + ty * 8 + i;
        if (grow < NN) {
#pragma unroll
            for (int j = 0; j < 4; j++) {
                float2 v = unpack2(acc[i][j]);
                *(float2*)&g_s1[(size_t)grow * NHID + 2 * tx + 32 * j] = v;
            }
        }
    }
}

// ---------------- SpMM1 + bias + ReLU: h = relu(A @ s1 + b1) ----------------
__global__ void spmm1_kernel(const int* __restrict__ acol, const float* __restrict__ aval,
                             const float* __restrict__ b1) {
    int warp = (blockIdx.x * blockDim.x + threadIdx.x) >> 5;
    int lane = threadIdx.x & 31;
    if (warp >= NN) return;

    int s = g_rowptr[warp];
    int e = g_rowptr[warp + 1];

    const float4* S1v = (const float4*)g_s1;
    float4 acc = make_float4(0.f, 0.f, 0.f, 0.f);

    int i = s;
    for (; i + 1 < e; i += 2) {
        int   c0 = __ldcs(&acol[i]);
        int   c1 = __ldcs(&acol[i + 1]);
        float v0 = __ldcs(&aval[i]);
        float v1 = __ldcs(&aval[i + 1]);
        float4 d0 = __ldcg(&S1v[(size_t)c0 * 32 + lane]);
        float4 d1 = __ldcg(&S1v[(size_t)c1 * 32 + lane]);
        acc.x += v0 * d0.x + v1 * d1.x;
        acc.y += v0 * d0.y + v1 * d1.y;
        acc.z += v0 * d0.z + v1 * d1.z;
        acc.w += v0 * d0.w + v1 * d1.w;
    }
    if (i < e) {
        int   c0 = __ldcs(&acol[i]);
        float v0 = __ldcs(&aval[i]);
        float4 d0 = __ldcg(&S1v[(size_t)c0 * 32 + lane]);
        acc.x += v0 * d0.x; acc.y += v0 * d0.y;
        acc.z += v0 * d0.z; acc.w += v0 * d0.w;
    }

    float4 b = ((const float4*)b1)[lane];
    acc.x = fmaxf(acc.x + b.x, 0.f);
    acc.y = fmaxf(acc.y + b.y, 0.f);
    acc.z = fmaxf(acc.z + b.z, 0.f);
    acc.w = fmaxf(acc.w + b.w, 0.f);
    __stcg(&((float4*)g_h)[(size_t)warp * 32 + lane], acc);
}

// ---------------- GEMM2: s2[N,40] = h[N,128] @ W2[128,40] ----------------
// Block: 256 rows, 256 threads; thread tile 8 rows (stride 32) x 5 cols.
#define G2_BM 256
#define G2_BK 32
#define G2_HS 33
__global__ void __launch_bounds__(256) gemm2_kernel(const float* __restrict__ W2) {
    __shared__ float Ws[NHID * NCLASS];     // 20 KB, resident whole kernel
    __shared__ float Hs[G2_BM * G2_HS];     // 33.8 KB, K-chunked

    const int tid  = threadIdx.x;
    const int rgrp = tid >> 3;              // 0..31
    const int cg   = tid & 7;               // cols cg*5 .. cg*5+4
    const int row0 = blockIdx.x * G2_BM;

    for (int j = tid; j < NHID * NCLASS; j += 256) Ws[j] = W2[j];

    float acc[8][5];
#pragma unroll
    for (int i = 0; i < 8; i++)
#pragma unroll
        for (int c = 0; c < 5; c++) acc[i][c] = 0.f;

    for (int k0 = 0; k0 < NHID; k0 += G2_BK) {
        // Hs: 256 rows x 32 cols = 2048 float4, 8 per thread
#pragma unroll
        for (int j = 0; j < 8; j++) {
            int fi = j * 256 + tid;
            int r  = fi >> 3;
            int c4 = (fi & 7) * 4;
            int grow = row0 + r;
            float4 v = make_float4(0.f, 0.f, 0.f, 0.f);
            if (grow < NN) v = *(const float4*)&g_h[(size_t)grow * NHID + k0 + c4];
            Hs[r * G2_HS + c4 + 0] = v.x;
            Hs[r * G2_HS + c4 + 1] = v.y;
            Hs[r * G2_HS + c4 + 2] = v.z;
            Hs[r * G2_HS + c4 + 3] = v.w;
        }
        __syncthreads();

#pragma unroll
        for (int kk = 0; kk < G2_BK; kk++) {
            float ws[5];
#pragma unroll
            for (int c = 0; c < 5; c++) ws[c] = Ws[(k0 + kk) * NCLASS + cg * 5 + c];
#pragma unroll
            for (int i = 0; i < 8; i++) {
                float hv = Hs[(rgrp + 32 * i) * G2_HS + kk];
#pragma unroll
                for (int c = 0; c < 5; c++) acc[i][c] += hv * ws[c];
            }
        }
        __syncthreads();
    }

#pragma unroll
    for (int i = 0; i < 8; i++) {
        int grow = row0 + rgrp + 32 * i;
        if (grow < NN) {
#pragma unroll
            for (int c = 0; c < 5; c++)
                g_s2[(size_t)grow * NCLASS + cg * 5 + c] = acc[i][c];
        }
    }
}

// ---------------- SpMM2 + bias + log_softmax ----------------
__global__ void spmm2_lsm_kernel(const int* __restrict__ acol, const float* __restrict__ aval,
                                 const float* __restrict__ b2, float* __restrict__ out) {
    int warp = (blockIdx.x * blockDim.x + threadIdx.x) >> 5;
    int lane = threadIdx.x & 31;
    if (warp >= NN) return;

    int s = g_rowptr[warp];
    int e = g_rowptr[warp + 1];
    bool active = lane < 20;

    const float2* S2v = (const float2*)g_s2;
    float2 acc = make_float2(0.f, 0.f);

    int i = s;
    for (; i + 1 < e; i += 2) {
        int   c0 = __ldcs(&acol[i]);
        int   c1 = __ldcs(&acol[i + 1]);
        float v0 = __ldcs(&aval[i]);
        float v1 = __ldcs(&aval[i + 1]);
        if (active) {
            float2 d0 = __ldcg(&S2v[(size_t)c0 * 20 + lane]);
            float2 d1 = __ldcg(&S2v[(size_t)c1 * 20 + lane]);
            acc.x += v0 * d0.x + v1 * d1.x;
            acc.y += v0 * d0.y + v1 * d1.y;
        }
    }
    if (i < e) {
        int   c0 = __ldcs(&acol[i]);
        float v0 = __ldcs(&aval[i]);
        if (active) {
            float2 d0 = __ldcg(&S2v[(size_t)c0 * 20 + lane]);
            acc.x += v0 * d0.x;
            acc.y += v0 * d0.y;
        }
    }

    if (active) {
        acc.x += __ldg(&b2[2 * lane]);
        acc.y += __ldg(&b2[2 * lane + 1]);
    }

    float m = active ? fmaxf(acc.x, acc.y) : -INFINITY;
#pragma unroll
    for (int off = 16; off > 0; off >>= 1)
        m = fmaxf(m, __shfl_xor_sync(0xFFFFFFFFu, m, off));

    float se = active ? (expf(acc.x - m) + expf(acc.y - m)) : 0.f;
#pragma unroll
    for (int off = 16; off > 0; off >>= 1)
        se += __shfl_xor_sync(0xFFFFFFFFu, se, off);

    float lse = m + logf(se);
    if (active) {
        out[(size_t)warp * NCLASS + 2 * lane]     = acc.x - lse;
        out[(size_t)warp * NCLASS + 2 * lane + 1] = acc.y - lse;
    }
}

// ---------------- launch ----------------
extern "C" void kernel_launch(void* const* d_in, const int* in_sizes, int n_in,
                              void* d_out, int out_size) {
    const float* x    = (const float*)d_in[0];
    const int*   arow = (const int*)  d_in[1];
    const int*   acol = (const int*)  d_in[2];
    const float* aval = (const float*)d_in[3];
    // d_in[4] = i (unused scalar)
    const float* W1 = (const float*)d_in[5];
    const float* b1 = (const float*)d_in[6];
    const float* W2 = (const float*)d_in[7];
    const float* b2 = (const float*)d_in[8];
    float* out = (float*)d_out;

    build_rowptr_kernel<<<(NN + 1 + 255) / 256, 256>>>(arow);
    gemm1_kernel<<<(NN + G1_BM - 1) / G1_BM, 256>>>(x, W1);
    spmm1_kernel<<<(NN * 32 + 255) / 256, 256>>>(acol, aval, b1);
    gemm2_kernel<<<(NN + G2_BM - 1) / G2_BM, 256>>>(W2);
    spmm2_lsm_kernel<<<(NN * 32 + 255) / 256, 256>>>(acol, aval, b2, out);
}